// round 3
// baseline (speedup 1.0000x reference)
#include <cuda_runtime.h>
#include <math.h>

#define C_   16
#define I_   64
#define H_   40
#define T_   512
#define G_   120
#define GP   128
#define BN   16
#define TCH  4
#define NTH  128
#define HS   24     // h row stride (floats), conflict-free update pattern
#define PRS  132    // preact row stride

// shared layout (float offsets)
#define SM_WIH 0                            // [64][128]
#define SM_WHH (SM_WIH + I_ * GP)           // [40][128]
#define SM_X   (SM_WHH + H_ * GP)           // [4][64][16]
#define SM_H   (SM_X + TCH * I_ * BN)       // [40][24]
#define SM_PIA (SM_H + H_ * HS)             // [2][16][132]  I-warp preacts (dbl buf)
#define SM_PIB (SM_PIA + 2 * BN * PRS)      // [16][132]     H-warp x-tail preacts
#define SM_PH  (SM_PIB + BN * PRS)          // [16][132]     H-warp hidden preacts
#define SM_TOT (SM_PH + BN * PRS)           // 26816 floats = 107264 B

typedef unsigned long long u64;

__device__ __forceinline__ u64 pack2(float lo, float hi) {
    u64 r;
    asm("mov.b64 %0, {%1, %2};"
        : "=l"(r) : "r"(__float_as_uint(lo)), "r"(__float_as_uint(hi)));
    return r;
}
__device__ __forceinline__ u64 dup2(float v) {
    u64 r;
    asm("mov.b64 %0, {%1, %1};" : "=l"(r) : "r"(__float_as_uint(v)));
    return r;
}
__device__ __forceinline__ u64 fma2(u64 a, u64 b, u64 c) {
    u64 d;
    asm("fma.rn.f32x2 %0, %1, %2, %3;" : "=l"(d) : "l"(a), "l"(b), "l"(c));
    return d;
}
__device__ __forceinline__ float sigf(float v) {
    return __fdividef(1.0f, 1.0f + __expf(-v));
}
__device__ __forceinline__ float tanh_fast(float a) {
    a = fminf(fmaxf(a, -15.0f), 15.0f);
    float e = __expf(2.0f * a);
    return __fdividef(e - 1.0f, e + 1.0f);
}

// accumulate 8 batches x 2 gate-pairs over k in [k0,k1): gate-pair vectorized
__device__ __forceinline__ void proj8(u64* a0, u64* a1,
                                      const float* __restrict__ wbase, // + 2*gt already
                                      const float* __restrict__ vbase, // batch-octet base
                                      int vstride, int k0, int k1)
{
    #pragma unroll 4
    for (int k = k0; k < k1; ++k) {
        u64 w0 = *(const u64*)(wbase + k * GP);
        u64 w1 = *(const u64*)(wbase + k * GP + 64);
        float4 va = *(const float4*)(vbase + k * vstride);
        float4 vb = *(const float4*)(vbase + k * vstride + 4);
        u64 d0 = dup2(va.x), d1 = dup2(va.y), d2 = dup2(va.z), d3 = dup2(va.w);
        u64 d4 = dup2(vb.x), d5 = dup2(vb.y), d6 = dup2(vb.z), d7 = dup2(vb.w);
        a0[0] = fma2(w0, d0, a0[0]); a1[0] = fma2(w1, d0, a1[0]);
        a0[1] = fma2(w0, d1, a0[1]); a1[1] = fma2(w1, d1, a1[1]);
        a0[2] = fma2(w0, d2, a0[2]); a1[2] = fma2(w1, d2, a1[2]);
        a0[3] = fma2(w0, d3, a0[3]); a1[3] = fma2(w1, d3, a1[3]);
        a0[4] = fma2(w0, d4, a0[4]); a1[4] = fma2(w1, d4, a1[4]);
        a0[5] = fma2(w0, d5, a0[5]); a1[5] = fma2(w1, d5, a1[5]);
        a0[6] = fma2(w0, d6, a0[6]); a1[6] = fma2(w1, d6, a1[6]);
        a0[7] = fma2(w0, d7, a0[7]); a1[7] = fma2(w1, d7, a1[7]);
    }
}

__device__ __forceinline__ void publish8(float* base, const u64* a0, const u64* a1)
{
    #pragma unroll
    for (int b = 0; b < 8; ++b) {
        *(u64*)(base + b * PRS)      = a0[b];
        *(u64*)(base + b * PRS + 64) = a1[b];
    }
}

__global__ void __launch_bounds__(NTH, 2)
gru_fused3_kernel(const float* __restrict__ x,
                  const float* __restrict__ Wih,
                  const float* __restrict__ Whh,
                  const float* __restrict__ bih,
                  const float* __restrict__ bhh,
                  const float* __restrict__ Wfc,
                  const float* __restrict__ bfc,
                  float* __restrict__ out)
{
    extern __shared__ float sm[];
    const int tid = threadIdx.x;
    const int c   = blockIdx.x & 15;
    const int b0  = (blockIdx.x >> 4) * BN;

    // ---- stage weights transposed to [k][g], g zero-padded to 128 ----
    for (int p = tid; p < I_ * GP; p += NTH) {
        int k = p >> 7, g = p & 127;
        sm[SM_WIH + p] = (g < G_) ? Wih[(c * G_ + g) * I_ + k] : 0.0f;
    }
    for (int p = tid; p < H_ * GP; p += NTH) {
        int k = p >> 7, g = p & 127;
        sm[SM_WHH + p] = (g < G_) ? Whh[(c * G_ + g) * H_ + k] : 0.0f;
    }
    for (int p = tid; p < H_ * HS; p += NTH) sm[SM_H + p] = 0.0f;
    __syncthreads();

    const int wid  = tid >> 5;
    const int gt   = tid & 31;
    const bool isI = (wid < 2);
    const int bh   = wid & 1;      // batch-octet index
    const int bq   = bh * 8;

    // ---- bias pairs (gate pad guarded) ----
    const int g0 = 2 * gt, g1 = 64 + 2 * gt;
    float bi1a = (g1     < G_) ? bih[c * G_ + g1]     : 0.0f;
    float bi1b = (g1 + 1 < G_) ? bih[c * G_ + g1 + 1] : 0.0f;
    float bh1a = (g1     < G_) ? bhh[c * G_ + g1]     : 0.0f;
    float bh1b = (g1 + 1 < G_) ? bhh[c * G_ + g1 + 1] : 0.0f;
    const u64 bI0 = pack2(bih[c * G_ + g0], bih[c * G_ + g0 + 1]);
    const u64 bI1 = pack2(bi1a, bi1b);
    const u64 bH0 = pack2(bhh[c * G_ + g0], bhh[c * G_ + g0 + 1]);
    const u64 bH1 = pack2(bh1a, bh1b);

    // staging lanes
    const int lb  = tid & 15;
    const int lig = tid >> 4;
    const float* xg = x + ((size_t)(b0 + lb) * C_ + c) * (size_t)(I_ * T_);

    const float* wI = sm + SM_WIH + 2 * gt;
    const float* wH = sm + SM_WHH + 2 * gt;

    int par = 0;
    for (int tc = 0; tc < T_; tc += TCH) {
        __syncthreads();
        // stage x chunk: x[b, c, i, tc..tc+3] -> sm_x[tt][i][b]
        #pragma unroll
        for (int r = 0; r < 8; ++r) {
            int i = lig + (r << 3);
            float4 v = *(const float4*)(xg + i * T_ + tc);
            float* xp = sm + SM_X + i * 16 + lb;     // tt stride = 1024 floats
            xp[0] = v.x; xp[1024] = v.y; xp[2048] = v.z; xp[3072] = v.w;
        }
        __syncthreads();

        #pragma unroll
        for (int tt = 0; tt < TCH; ++tt) {
            const float* xr = sm + SM_X + tt * 1024 + bq;
            if (isI) {
                // ---- producer: input projection k = 0..51 ----
                u64 a0[8], a1[8];
                #pragma unroll
                for (int b = 0; b < 8; ++b) { a0[b] = bI0; a1[b] = bI1; }
                proj8(a0, a1, wI, xr, 16, 0, 52);
                publish8(sm + SM_PIA + par * (BN * PRS) + bq * PRS + 2 * gt, a0, a1);
                asm volatile("bar.sync %0, 64;" :: "r"(1 + bh) : "memory");
            } else {
                // ---- consumer: x tail k = 52..63 ----
                u64 a0[8], a1[8];
                #pragma unroll
                for (int b = 0; b < 8; ++b) { a0[b] = 0ull; a1[b] = 0ull; }
                proj8(a0, a1, wI, xr, 16, 52, 64);
                publish8(sm + SM_PIB + bq * PRS + 2 * gt, a0, a1);
                // ---- hidden projection k = 0..39 ----
                #pragma unroll
                for (int b = 0; b < 8; ++b) { a0[b] = bH0; a1[b] = bH1; }
                proj8(a0, a1, wH, sm + SM_H + bq, HS, 0, 40);
                publish8(sm + SM_PH + bq * PRS + 2 * gt, a0, a1);
                asm volatile("bar.sync %0, 64;" :: "r"(1 + bh) : "memory");

                // ---- gate combine + h update (this warp's 8 batches) ----
                const int bl  = bq + (gt & 7);
                const int hb0 = gt >> 3;
                const float* pa = sm + SM_PIA + par * (BN * PRS) + bl * PRS;
                const float* pb = sm + SM_PIB + bl * PRS;
                const float* ph = sm + SM_PH + bl * PRS;
                float* hcol = sm + SM_H + bl;
                #pragma unroll
                for (int q = 0; q < 10; ++q) {
                    int hh = hb0 + 4 * q;
                    float rg = sigf(pa[hh]      + pb[hh]      + ph[hh]);
                    float zg = sigf(pa[40 + hh] + pb[40 + hh] + ph[40 + hh]);
                    float ng = tanh_fast(pa[80 + hh] + pb[80 + hh]
                                         + rg * ph[80 + hh]);
                    float ho = hcol[hh * HS];
                    hcol[hh * HS] = ng + zg * (ho - ng);
                }
                __syncwarp();
            }
            par ^= 1;
        }
    }

    __syncthreads();
    // ---- FC head ----
    if (tid < BN) {
        float acc = bfc[c];
        #pragma unroll
        for (int h2 = 0; h2 < H_; ++h2)
            acc += sm[SM_H + h2 * HS + tid] * Wfc[c * H_ + h2];
        out[(size_t)(b0 + tid) * C_ + c] = sigf(acc);
    }
}

extern "C" void kernel_launch(void* const* d_in, const int* in_sizes, int n_in,
                              void* d_out, int out_size)
{
    const float* x   = (const float*)d_in[0];
    const float* Wih = (const float*)d_in[1];
    const float* Whh = (const float*)d_in[2];
    const float* bih = (const float*)d_in[3];
    const float* bhh = (const float*)d_in[4];
    const float* Wfc = (const float*)d_in[5];
    const float* bfc = (const float*)d_in[6];
    float* out = (float*)d_out;

    const int smem_bytes = SM_TOT * (int)sizeof(float);   // 107264
    cudaFuncSetAttribute(gru_fused3_kernel,
                         cudaFuncAttributeMaxDynamicSharedMemorySize, smem_bytes);
    gru_fused3_kernel<<<256, NTH, smem_bytes>>>(x, Wih, Whh, bih, bhh, Wfc, bfc, out);
}

// round 4
// speedup vs baseline: 1.0085x; 1.0085x over previous
#include <cuda_runtime.h>
#include <math.h>

#define C_   16
#define I_   64
#define H_   40
#define T_   512
#define G_   120
#define GP   128
#define BN   32      // batches per CTA
#define TCH  16      // timesteps staged per chunk
#define NTH  128
#define HS   40      // h row stride: bank = 8*hh + lane pattern, conflict-free
#define PRS  132     // S row stride
#define HNS  44      // Hn row stride

// shared layout (float offsets)
#define SM_WIH 0                          // [64][128]
#define SM_WHH (SM_WIH + I_ * GP)         // [40][128]
#define SM_X   (SM_WHH + H_ * GP)         // 4 warps x [16][64][8]
#define SM_H   (SM_X + 4 * TCH * I_ * 8)  // [40][40]
#define SM_S   (SM_H + H_ * HS)           // [32][132]
#define SM_HN  (SM_S + BN * PRS)          // [32][44]
#define SM_TOT (SM_HN + BN * HNS)         // 53312 floats = 213248 B

typedef unsigned long long u64;

__device__ __forceinline__ u64 pack2(float lo, float hi) {
    u64 r;
    asm("mov.b64 %0, {%1, %2};"
        : "=l"(r) : "r"(__float_as_uint(lo)), "r"(__float_as_uint(hi)));
    return r;
}
__device__ __forceinline__ u64 dup2(float v) {
    u64 r;
    asm("mov.b64 %0, {%1, %1};" : "=l"(r) : "r"(__float_as_uint(v)));
    return r;
}
__device__ __forceinline__ u64 fma2(u64 a, u64 b, u64 c) {
    u64 d;
    asm("fma.rn.f32x2 %0, %1, %2, %3;" : "=l"(d) : "l"(a), "l"(b), "l"(c));
    return d;
}
__device__ __forceinline__ u64 add2(u64 a, u64 b) {
    u64 d;
    asm("add.rn.f32x2 %0, %1, %2;" : "=l"(d) : "l"(a), "l"(b));
    return d;
}
__device__ __forceinline__ float sigf(float v) {
    return __fdividef(1.0f, 1.0f + __expf(-v));
}
__device__ __forceinline__ float tanh_fast(float a) {
    a = fminf(fmaxf(a, -15.0f), 15.0f);
    float e = __expf(2.0f * a);
    return __fdividef(e - 1.0f, e + 1.0f);
}

// 8 batches x 2 gate-pairs accumulate over [k0,k1)
__device__ __forceinline__ void proj8(u64* a0, u64* a1,
                                      const float* __restrict__ wbase, // +2*gt
                                      const float* __restrict__ vbase,
                                      int vstride, int k0, int k1)
{
    #pragma unroll 4
    for (int k = k0; k < k1; ++k) {
        u64 w0 = *(const u64*)(wbase + k * GP);
        u64 w1 = *(const u64*)(wbase + k * GP + 64);
        float4 va = *(const float4*)(vbase + k * vstride);
        float4 vb = *(const float4*)(vbase + k * vstride + 4);
        u64 d0 = dup2(va.x), d1 = dup2(va.y), d2 = dup2(va.z), d3 = dup2(va.w);
        u64 d4 = dup2(vb.x), d5 = dup2(vb.y), d6 = dup2(vb.z), d7 = dup2(vb.w);
        a0[0] = fma2(w0, d0, a0[0]); a1[0] = fma2(w1, d0, a1[0]);
        a0[1] = fma2(w0, d1, a0[1]); a1[1] = fma2(w1, d1, a1[1]);
        a0[2] = fma2(w0, d2, a0[2]); a1[2] = fma2(w1, d2, a1[2]);
        a0[3] = fma2(w0, d3, a0[3]); a1[3] = fma2(w1, d3, a1[3]);
        a0[4] = fma2(w0, d4, a0[4]); a1[4] = fma2(w1, d4, a1[4]);
        a0[5] = fma2(w0, d5, a0[5]); a1[5] = fma2(w1, d5, a1[5]);
        a0[6] = fma2(w0, d6, a0[6]); a1[6] = fma2(w1, d6, a1[6]);
        a0[7] = fma2(w0, d7, a0[7]); a1[7] = fma2(w1, d7, a1[7]);
    }
}

__global__ void __launch_bounds__(NTH, 1)
gru_fused4_kernel(const float* __restrict__ x,
                  const float* __restrict__ Wih,
                  const float* __restrict__ Whh,
                  const float* __restrict__ bih,
                  const float* __restrict__ bhh,
                  const float* __restrict__ Wfc,
                  const float* __restrict__ bfc,
                  float* __restrict__ out)
{
    extern __shared__ float sm[];
    const int tid = threadIdx.x;
    const int c   = blockIdx.x & 15;
    const int b0  = (blockIdx.x >> 4) * BN;

    // stage weights transposed [k][g], g zero-padded to 128
    for (int p = tid; p < I_ * GP; p += NTH) {
        int k = p >> 7, g = p & 127;
        sm[SM_WIH + p] = (g < G_) ? Wih[(c * G_ + g) * I_ + k] : 0.0f;
    }
    for (int p = tid; p < H_ * GP; p += NTH) {
        int k = p >> 7, g = p & 127;
        sm[SM_WHH + p] = (g < G_) ? Whh[(c * G_ + g) * H_ + k] : 0.0f;
    }
    for (int p = tid; p < H_ * HS; p += NTH) sm[SM_H + p] = 0.0f;
    __syncthreads();

    const int wid = tid >> 5;
    const int gt  = tid & 31;
    const int bq  = wid * 8;               // this warp's batch octet

    // biases: fold bih+bhh pairs into accumulator init (aI gets bI, aH gets bH)
    const int g0 = 2 * gt, g1 = 64 + 2 * gt;
    float bi1a = (g1     < G_) ? bih[c * G_ + g1]     : 0.0f;
    float bi1b = (g1 + 1 < G_) ? bih[c * G_ + g1 + 1] : 0.0f;
    float bh1a = (g1     < G_) ? bhh[c * G_ + g1]     : 0.0f;
    float bh1b = (g1 + 1 < G_) ? bhh[c * G_ + g1 + 1] : 0.0f;
    const u64 bI0 = pack2(bih[c * G_ + g0], bih[c * G_ + g0 + 1]);
    const u64 bI1 = pack2(bi1a, bi1b);
    const u64 bH0 = pack2(bhh[c * G_ + g0], bhh[c * G_ + g0 + 1]);
    const u64 bH1 = pack2(bh1a, bh1b);

    const float* wI = sm + SM_WIH + 2 * gt;
    const float* wH = sm + SM_WHH + 2 * gt;
    float* Xw = sm + SM_X + wid * (TCH * I_ * 8);

    // staging lane mapping: lb = gt>>2 (batch 0..7), li = gt&3 (i phase)
    const int lb = gt >> 2;
    const int li = gt & 3;
    const float* xg = x + ((size_t)(b0 + bq + lb) * C_ + c) * (size_t)(I_ * T_);

    // combine lane mapping
    const int blc = bq + (gt & 7);
    const int hb  = gt >> 3;               // 0..3
    const bool hnw = (gt >= 8) && (gt < 28);   // lanes owning n-gate pairs in g1

    for (int tc = 0; tc < T_; tc += TCH) {
        // ---- warp-local staging: x[b, c, i, tc..tc+15] -> Xw[tt][i][lb] ----
        #pragma unroll 4
        for (int r = 0; r < 16; ++r) {
            int i = li + 4 * r;
            const float* gp = xg + i * T_ + tc;
            float4 v0 = *(const float4*)(gp);
            float4 v1 = *(const float4*)(gp + 4);
            float4 v2 = *(const float4*)(gp + 8);
            float4 v3 = *(const float4*)(gp + 12);
            float* xp = Xw + i * 8 + lb;          // tt stride = 512
            xp[0*512]  = v0.x; xp[1*512]  = v0.y; xp[2*512]  = v0.z; xp[3*512]  = v0.w;
            xp[4*512]  = v1.x; xp[5*512]  = v1.y; xp[6*512]  = v1.z; xp[7*512]  = v1.w;
            xp[8*512]  = v2.x; xp[9*512]  = v2.y; xp[10*512] = v2.z; xp[11*512] = v2.w;
            xp[12*512] = v3.x; xp[13*512] = v3.y; xp[14*512] = v3.z; xp[15*512] = v3.w;
        }
        __syncwarp();

        for (int tt = 0; tt < TCH; ++tt) {
            u64 aI[2][8], aH[2][8];
            #pragma unroll
            for (int b = 0; b < 8; ++b) {
                aI[0][b] = bI0; aI[1][b] = bI1;
                aH[0][b] = bH0; aH[1][b] = bH1;
            }

            proj8(aI[0], aI[1], wI, Xw + tt * 512, 8, 0, I_);
            proj8(aH[0], aH[1], wH, sm + SM_H + bq, HS, 0, H_);

            // publish S = aI + aH, and Hn (h-part of n-gates) for g1 in [80,120)
            #pragma unroll
            for (int b = 0; b < 8; ++b) {
                float* ps = sm + SM_S + (bq + b) * PRS + 2 * gt;
                *(u64*)ps        = add2(aI[0][b], aH[0][b]);
                *(u64*)(ps + 64) = add2(aI[1][b], aH[1][b]);
                if (hnw)
                    *(u64*)(sm + SM_HN + (bq + b) * HNS + 2 * (gt - 8)) = aH[1][b];
            }
            __syncwarp();

            // combine: this warp's 8 batches x 40 h (10 items/lane)
            {
                const float* S  = sm + SM_S  + blc * PRS;
                const float* Hn = sm + SM_HN + blc * HNS;
                float* hcol = sm + SM_H + blc - bq + bq;   // = sm + SM_H + blc
                #pragma unroll
                for (int q = 0; q < 10; ++q) {
                    int hh = hb + 4 * q;
                    float rg = sigf(S[hh]);
                    float zg = sigf(S[40 + hh]);
                    float hn = Hn[hh];
                    float ng = tanh_fast(fmaf(rg - 1.0f, hn, S[80 + hh]));
                    float* hp = sm + SM_H + hh * HS + blc;
                    float ho = *hp;
                    *hp = ng + zg * (ho - ng);
                }
            }
            __syncwarp();
        }
    }

    __syncthreads();
    // FC head: y[b,c] = sigmoid(h . W_fc[c] + b_fc[c])
    if (tid < BN) {
        float acc = bfc[c];
        #pragma unroll
        for (int h2 = 0; h2 < H_; ++h2)
            acc += sm[SM_H + h2 * HS + tid] * Wfc[c * H_ + h2];
        out[(size_t)(b0 + tid) * C_ + c] = sigf(acc);
    }
}

extern "C" void kernel_launch(void* const* d_in, const int* in_sizes, int n_in,
                              void* d_out, int out_size)
{
    const float* x   = (const float*)d_in[0];
    const float* Wih = (const float*)d_in[1];
    const float* Whh = (const float*)d_in[2];
    const float* bih = (const float*)d_in[3];
    const float* bhh = (const float*)d_in[4];
    const float* Wfc = (const float*)d_in[5];
    const float* bfc = (const float*)d_in[6];
    float* out = (float*)d_out;

    const int smem_bytes = SM_TOT * (int)sizeof(float);   // 213248
    cudaFuncSetAttribute(gru_fused4_kernel,
                         cudaFuncAttributeMaxDynamicSharedMemorySize, smem_bytes);
    gru_fused4_kernel<<<128, NTH, smem_bytes>>>(x, Wih, Whh, bih, bhh, Wfc, bfc, out);
}

// round 5
// speedup vs baseline: 1.2146x; 1.2044x over previous
#include <cuda_runtime.h>
#include <math.h>

#define C_   16
#define I_   64
#define H_   40
#define T_   512
#define G_   120
#define GP   128
#define BN   16
#define TCH  4
#define NTH  128
#define HS   20     // h row stride
#define PRS  132    // gi/gh row stride

// shared layout (float offsets)
#define SM_WIH 0                           // [64][128]
#define SM_WHH (SM_WIH + I_ * GP)          // [40][128]
#define SM_X   (SM_WHH + H_ * GP)          // [4][64][16]
#define SM_H   (SM_X + TCH * I_ * BN)      // [40][20]
#define SM_GI  (SM_H + H_ * HS)            // [4][16][132] input-projection results
#define SM_GH  (SM_GI + TCH * BN * PRS)    // [16][132]    hidden-projection (per step)
#define SM_TOT (SM_GH + BN * PRS)          // 28768 floats = 115072 B

typedef unsigned long long u64;

__device__ __forceinline__ u64 pack2(float lo, float hi) {
    u64 r;
    asm("mov.b64 %0, {%1, %2};"
        : "=l"(r) : "r"(__float_as_uint(lo)), "r"(__float_as_uint(hi)));
    return r;
}
__device__ __forceinline__ u64 dup2(float v) {
    u64 r;
    asm("mov.b64 %0, {%1, %1};" : "=l"(r) : "r"(__float_as_uint(v)));
    return r;
}
__device__ __forceinline__ u64 fma2(u64 a, u64 b, u64 c) {
    u64 d;
    asm("fma.rn.f32x2 %0, %1, %2, %3;" : "=l"(d) : "l"(a), "l"(b), "l"(c));
    return d;
}
__device__ __forceinline__ float sigf(float v) {
    return __fdividef(1.0f, 1.0f + __expf(-v));
}
__device__ __forceinline__ float tanh_fast(float a) {
    a = fminf(fmaxf(a, -15.0f), 15.0f);
    float e = __expf(2.0f * a);
    return __fdividef(e - 1.0f, e + 1.0f);
}

__global__ void __launch_bounds__(NTH, 2)
gru_fused5_kernel(const float* __restrict__ x,
                  const float* __restrict__ Wih,
                  const float* __restrict__ Whh,
                  const float* __restrict__ bih,
                  const float* __restrict__ bhh,
                  const float* __restrict__ Wfc,
                  const float* __restrict__ bfc,
                  float* __restrict__ out)
{
    extern __shared__ float sm[];
    const int tid = threadIdx.x;
    const int c   = blockIdx.x & 15;
    const int b0  = (blockIdx.x >> 4) * BN;

    // ---- stage weights transposed [k][g], g zero-padded to 128 ----
    for (int p = tid; p < I_ * GP; p += NTH) {
        int k = p >> 7, g = p & 127;
        sm[SM_WIH + p] = (g < G_) ? Wih[(c * G_ + g) * I_ + k] : 0.0f;
    }
    for (int p = tid; p < H_ * GP; p += NTH) {
        int k = p >> 7, g = p & 127;
        sm[SM_WHH + p] = (g < G_) ? Whh[(c * G_ + g) * H_ + k] : 0.0f;
    }
    for (int p = tid; p < H_ * HS; p += NTH) sm[SM_H + p] = 0.0f;
    __syncthreads();

    const int wid = tid >> 5;
    const int gt  = tid & 31;
    const int bq  = wid * 4;               // this warp's batch quad (phase B)

    // ---- bias pairs (zero-padded gate guard) ----
    const int g0 = 2 * gt, g1 = 64 + 2 * gt;
    float bi1a = (g1     < G_) ? bih[c * G_ + g1]     : 0.0f;
    float bi1b = (g1 + 1 < G_) ? bih[c * G_ + g1 + 1] : 0.0f;
    float bh1a = (g1     < G_) ? bhh[c * G_ + g1]     : 0.0f;
    float bh1b = (g1 + 1 < G_) ? bhh[c * G_ + g1 + 1] : 0.0f;
    const u64 bI0 = pack2(bih[c * G_ + g0], bih[c * G_ + g0 + 1]);
    const u64 bI1 = pack2(bi1a, bi1b);
    const u64 bH0 = pack2(bhh[c * G_ + g0], bhh[c * G_ + g0 + 1]);
    const u64 bH1 = pack2(bh1a, bh1b);

    const float* wI = sm + SM_WIH + 2 * gt;
    const float* wH = sm + SM_WHH + 2 * gt;

    // x staging lanes: b = tid&15, i-phase = tid>>4 (+8r)
    const int lb  = tid & 15;
    const int lig = tid >> 4;
    const float* xg = x + ((size_t)(b0 + lb) * C_ + c) * (size_t)(I_ * T_);

    // combine lane mapping (phase B): 4 batches x 40 h = 5 items/lane
    const int bl = bq + (gt >> 3);
    const int hb = gt & 7;

    for (int tc = 0; tc < T_; tc += TCH) {
        // ---- stage x chunk: x[b, c, i, tc..tc+3] -> X[tt][i][b] ----
        #pragma unroll
        for (int r = 0; r < 8; ++r) {
            int i = lig + (r << 3);
            float4 v = *(const float4*)(xg + i * T_ + tc);
            float* xp = sm + SM_X + i * 16 + lb;       // tt stride = 1024
            xp[0] = v.x; xp[1024] = v.y; xp[2048] = v.z; xp[3072] = v.w;
        }
        __syncthreads();

        // ---- phase A: warp `wid` computes gi[tt=wid] for all 16 batches ----
        {
            u64 a0[16], a1[16];
            #pragma unroll
            for (int b = 0; b < 16; ++b) { a0[b] = bI0; a1[b] = bI1; }
            const float* xr = sm + SM_X + wid * 1024;
            #pragma unroll 4
            for (int k = 0; k < I_; ++k) {
                u64 w0 = *(const u64*)(wI + k * GP);
                u64 w1 = *(const u64*)(wI + k * GP + 64);
                const float* xk = xr + k * 16;
                float4 xa = *(const float4*)(xk);
                float4 xb = *(const float4*)(xk + 4);
                float4 xc = *(const float4*)(xk + 8);
                float4 xd = *(const float4*)(xk + 12);
                u64 d0 = dup2(xa.x), d1 = dup2(xa.y), d2 = dup2(xa.z), d3 = dup2(xa.w);
                u64 d4 = dup2(xb.x), d5 = dup2(xb.y), d6 = dup2(xb.z), d7 = dup2(xb.w);
                u64 d8 = dup2(xc.x), d9 = dup2(xc.y), da = dup2(xc.z), db = dup2(xc.w);
                u64 dc = dup2(xd.x), dd = dup2(xd.y), de = dup2(xd.z), df = dup2(xd.w);
                a0[0]  = fma2(w0, d0, a0[0]);  a1[0]  = fma2(w1, d0, a1[0]);
                a0[1]  = fma2(w0, d1, a0[1]);  a1[1]  = fma2(w1, d1, a1[1]);
                a0[2]  = fma2(w0, d2, a0[2]);  a1[2]  = fma2(w1, d2, a1[2]);
                a0[3]  = fma2(w0, d3, a0[3]);  a1[3]  = fma2(w1, d3, a1[3]);
                a0[4]  = fma2(w0, d4, a0[4]);  a1[4]  = fma2(w1, d4, a1[4]);
                a0[5]  = fma2(w0, d5, a0[5]);  a1[5]  = fma2(w1, d5, a1[5]);
                a0[6]  = fma2(w0, d6, a0[6]);  a1[6]  = fma2(w1, d6, a1[6]);
                a0[7]  = fma2(w0, d7, a0[7]);  a1[7]  = fma2(w1, d7, a1[7]);
                a0[8]  = fma2(w0, d8, a0[8]);  a1[8]  = fma2(w1, d8, a1[8]);
                a0[9]  = fma2(w0, d9, a0[9]);  a1[9]  = fma2(w1, d9, a1[9]);
                a0[10] = fma2(w0, da, a0[10]); a1[10] = fma2(w1, da, a1[10]);
                a0[11] = fma2(w0, db, a0[11]); a1[11] = fma2(w1, db, a1[11]);
                a0[12] = fma2(w0, dc, a0[12]); a1[12] = fma2(w1, dc, a1[12]);
                a0[13] = fma2(w0, dd, a0[13]); a1[13] = fma2(w1, dd, a1[13]);
                a0[14] = fma2(w0, de, a0[14]); a1[14] = fma2(w1, de, a1[14]);
                a0[15] = fma2(w0, df, a0[15]); a1[15] = fma2(w1, df, a1[15]);
            }
            float* gw = sm + SM_GI + wid * (BN * PRS) + 2 * gt;
            #pragma unroll
            for (int b = 0; b < 16; ++b) {
                *(u64*)(gw + b * PRS)      = a0[b];
                *(u64*)(gw + b * PRS + 64) = a1[b];
            }
        }
        __syncthreads();

        // ---- phase B: 4 sequential steps, warp-local on its 4 batches ----
        #pragma unroll
        for (int tt = 0; tt < TCH; ++tt) {
            u64 a0[4], a1[4];
            #pragma unroll
            for (int b = 0; b < 4; ++b) { a0[b] = bH0; a1[b] = bH1; }
            const float* hrow = sm + SM_H + bq;
            #pragma unroll 8
            for (int k = 0; k < H_; ++k) {
                u64 w0 = *(const u64*)(wH + k * GP);
                u64 w1 = *(const u64*)(wH + k * GP + 64);
                float4 hv = *(const float4*)(hrow + k * HS);
                u64 d0 = dup2(hv.x), d1 = dup2(hv.y), d2 = dup2(hv.z), d3 = dup2(hv.w);
                a0[0] = fma2(w0, d0, a0[0]); a1[0] = fma2(w1, d0, a1[0]);
                a0[1] = fma2(w0, d1, a0[1]); a1[1] = fma2(w1, d1, a1[1]);
                a0[2] = fma2(w0, d2, a0[2]); a1[2] = fma2(w1, d2, a1[2]);
                a0[3] = fma2(w0, d3, a0[3]); a1[3] = fma2(w1, d3, a1[3]);
            }
            // publish gh (warp-private rows)
            #pragma unroll
            for (int b = 0; b < 4; ++b) {
                float* pg = sm + SM_GH + (bq + b) * PRS + 2 * gt;
                *(u64*)pg        = a0[b];
                *(u64*)(pg + 64) = a1[b];
            }
            __syncwarp();

            // combine + h update
            {
                const float* gi = sm + SM_GI + tt * (BN * PRS) + bl * PRS;
                const float* gh = sm + SM_GH + bl * PRS;
                #pragma unroll
                for (int q = 0; q < 5; ++q) {
                    int hh = hb + 8 * q;
                    float rg = sigf(gi[hh]      + gh[hh]);
                    float zg = sigf(gi[40 + hh] + gh[40 + hh]);
                    float ng = tanh_fast(gi[80 + hh] + rg * gh[80 + hh]);
                    float* hp = sm + SM_H + hh * HS + bl;
                    float ho = *hp;
                    *hp = ng + zg * (ho - ng);
                }
            }
            __syncwarp();
        }
    }

    __syncthreads();
    // ---- FC head ----
    if (tid < BN) {
        float acc = bfc[c];
        #pragma unroll
        for (int h2 = 0; h2 < H_; ++h2)
            acc += sm[SM_H + h2 * HS + tid] * Wfc[c * H_ + h2];
        out[(size_t)(b0 + tid) * C_ + c] = sigf(acc);
    }
}

extern "C" void kernel_launch(void* const* d_in, const int* in_sizes, int n_in,
                              void* d_out, int out_size)
{
    const float* x   = (const float*)d_in[0];
    const float* Wih = (const float*)d_in[1];
    const float* Whh = (const float*)d_in[2];
    const float* bih = (const float*)d_in[3];
    const float* bhh = (const float*)d_in[4];
    const float* Wfc = (const float*)d_in[5];
    const float* bfc = (const float*)d_in[6];
    float* out = (float*)d_out;

    const int smem_bytes = SM_TOT * (int)sizeof(float);   // 115072
    cudaFuncSetAttribute(gru_fused5_kernel,
                         cudaFuncAttributeMaxDynamicSharedMemorySize, smem_bytes);
    gru_fused5_kernel<<<256, NTH, smem_bytes>>>(x, Wih, Whh, bih, bhh, Wfc, bfc, out);
}